// round 5
// baseline (speedup 1.0000x reference)
#include <cuda_runtime.h>
#include <cuda_bf16.h>
#include <math.h>
#include <stdint.h>

#define Nn 20000
#define Dd 256
#define Ss 4
#define Ee 320000
#define Hh 5
#define SN (Ss * Nn)

// ---------------- scratch (device globals; no allocs allowed) ----------------
__device__ float g_deg[Nn];
__device__ float g_dinv[Nn];
__device__ int   g_cnt[Nn];
__device__ int   g_rowp[Nn + 1];
__device__ int   g_fill[Nn];
__device__ int   g_csrc[Ee];
__device__ float g_cnorm[Ee];

__device__ float g_tmpW[SN * Dd];
__device__ float g_giAll[SN * 3 * Dd];
__device__ float g_gh[Nn * 3 * Dd];
__device__ float g_h1[Nn * Dd];
__device__ float g_h2[Nn * Dd];
__device__ float g_f2[Nn * 64];
__device__ float g_d1[Nn * 64];

// split-bf16 activations: layout [rows, 2K] = [hi | lo]
__device__ __nv_bfloat16 g_xs[SN * 512];
__device__ __nv_bfloat16 g_aggA[SN * 512];
__device__ __nv_bfloat16 g_seqs[SN * 512];
__device__ __nv_bfloat16 g_hs[Nn * 512];
__device__ __nv_bfloat16 g_f1s[Nn * 256];

// split-bf16 weights: [M, 2K]
__device__ __nv_bfloat16 g_gcnWs[3 * 256 * 512];
__device__ __nv_bfloat16 g_Wihs[768 * 512];
__device__ __nv_bfloat16 g_Whhs[768 * 512];
__device__ __nv_bfloat16 g_fc1Ws[128 * 512];
__device__ __nv_bfloat16 g_fc2Ws[64 * 256];
__device__ __nv_bfloat16 g_dh1Ws[64 * 512];

// ---------------- helpers ----------------
__device__ __forceinline__ void split_write(float v, __nv_bfloat16* hi, __nv_bfloat16* lo) {
    __nv_bfloat16 h = __float2bfloat16(v);
    *hi = h;
    *lo = __float2bfloat16(v - __bfloat162float(h));
}
__device__ __forceinline__ void ldsm4(uint32_t* r, uint32_t addr) {
    asm volatile("ldmatrix.sync.aligned.m8n8.x4.shared.b16 {%0,%1,%2,%3}, [%4];"
                 : "=r"(r[0]), "=r"(r[1]), "=r"(r[2]), "=r"(r[3]) : "r"(addr));
}
__device__ __forceinline__ void mma16816(float* c, const uint32_t* a, const uint32_t* b) {
    asm volatile(
        "mma.sync.aligned.m16n8k16.row.col.f32.bf16.bf16.f32 "
        "{%0,%1,%2,%3}, {%4,%5,%6,%7}, {%8,%9}, {%0,%1,%2,%3};"
        : "+f"(c[0]), "+f"(c[1]), "+f"(c[2]), "+f"(c[3])
        : "r"(a[0]), "r"(a[1]), "r"(a[2]), "r"(a[3]), "r"(b[0]), "r"(b[1]));
}
__device__ __forceinline__ void cpa16z(uint32_t dst, const void* src, int sz) {
    asm volatile("cp.async.cg.shared.global [%0], [%1], 16, %2;"
                 :: "r"(dst), "l"(src), "r"(sz));
}

// ---------------- graph preprocessing ----------------
__global__ void k_init_deg_cnt() {
    int i = blockIdx.x * blockDim.x + threadIdx.x;
    if (i < Nn) { g_deg[i] = 1.0f; g_cnt[i] = 0; }
}
__global__ void k_edge_deg_cnt(const int* __restrict__ dst, const float* __restrict__ w) {
    int e = blockIdx.x * blockDim.x + threadIdx.x;
    if (e < Ee) {
        int t = dst[e];
        atomicAdd(&g_deg[t], w[e]);
        atomicAdd(&g_cnt[t], 1);
    }
}
__global__ void k_dinv() {
    int i = blockIdx.x * blockDim.x + threadIdx.x;
    if (i < Nn) g_dinv[i] = rsqrtf(g_deg[i]);
}
__global__ void k_scan() {
    __shared__ int wsum[32];
    __shared__ int carry_sh;
    if (threadIdx.x == 0) carry_sh = 0;
    __syncthreads();
    const int lane = threadIdx.x & 31, wid = threadIdx.x >> 5;
    const int nw = blockDim.x >> 5;
    for (int base = 0; base < Nn; base += blockDim.x) {
        int i = base + threadIdx.x;
        int v = (i < Nn) ? g_cnt[i] : 0;
        int x = v;
#pragma unroll
        for (int o = 1; o < 32; o <<= 1) {
            int y = __shfl_up_sync(0xffffffffu, x, o);
            if (lane >= o) x += y;
        }
        if (lane == 31) wsum[wid] = x;
        __syncthreads();
        if (wid == 0) {
            int s = (lane < nw) ? wsum[lane] : 0;
#pragma unroll
            for (int o = 1; o < 32; o <<= 1) {
                int y = __shfl_up_sync(0xffffffffu, s, o);
                if (lane >= o) s += y;
            }
            wsum[lane] = s;
        }
        __syncthreads();
        int warp_off = (wid == 0) ? 0 : wsum[wid - 1];
        int carry = carry_sh;
        if (i < Nn) g_rowp[i] = carry + warp_off + x - v;
        __syncthreads();
        if (threadIdx.x == blockDim.x - 1) carry_sh = carry + wsum[nw - 1];
        __syncthreads();
    }
    if (threadIdx.x == 0) g_rowp[Nn] = carry_sh;
}
__global__ void k_copy_fill() {
    int i = blockIdx.x * blockDim.x + threadIdx.x;
    if (i < Nn) g_fill[i] = g_rowp[i];
}
__global__ void k_fill_csr(const int* __restrict__ src, const int* __restrict__ dst,
                           const float* __restrict__ w) {
    int e = blockIdx.x * blockDim.x + threadIdx.x;
    if (e < Ee) {
        int s = src[e], t = dst[e];
        int pos = atomicAdd(&g_fill[t], 1);
        g_csrc[pos]  = s;
        g_cnorm[pos] = g_dinv[s] * w[e] * g_dinv[t];
    }
}

// ---------------- split conversion kernels ----------------
__global__ void k_split(const float* __restrict__ in, __nv_bfloat16* __restrict__ out,
                        long total, int K) {
    long idx = (long)blockIdx.x * blockDim.x + threadIdx.x;
    if (idx >= total) return;
    long r = idx / K;
    int  c = (int)(idx - r * K);
    float v = in[idx];
    split_write(v, &out[r * 2 * K + c], &out[r * 2 * K + K + c]);
}
__global__ void k_splitT(const float* __restrict__ in, __nv_bfloat16* __restrict__ out,
                         int Kd, int Md) {
    long idx = (long)blockIdx.x * blockDim.x + threadIdx.x;
    if (idx >= (long)Kd * Md) return;
    int k = (int)(idx / Md);
    int m = (int)(idx - (long)k * Md);
    float v = in[idx];
    split_write(v, &out[(long)m * 2 * Kd + k], &out[(long)m * 2 * Kd + Kd + k]);
}

// ---------------- bf16 mma.sync GEMM with 3-term split ----------------
// C[R,M] = A[R,K] @ B[M,K]^T; A/B split: [rows, 2K] = [hi | lo].
// Block 128x128, K-chunk 64; 256 thr, 8 warps (2M x 4N), warp 64x32.
// 3-stage cp.async pipeline, 1 barrier per chunk, ldsm software pipeline.
#define SROW 72
#define AB_HALF (128 * SROW * 2)          // bytes of one array (A or B) per stage
#define STAGE_BYTES (2 * AB_HALF)         // A+B per stage = 36864
#define GEMM_SMEM (3 * STAGE_BYTES)       // 110592
__global__ void __launch_bounds__(256)
gemm_mma(const __nv_bfloat16* __restrict__ A, const __nv_bfloat16* __restrict__ B,
         const float* __restrict__ bias, float* __restrict__ outF,
         __nv_bfloat16* __restrict__ outS, int R, int M, int K, int ACT, int MODE) {
    extern __shared__ __align__(16) __nv_bfloat16 smg[];
    const uint32_t sbase = (uint32_t)__cvta_generic_to_shared(smg);

    const int tid  = threadIdx.x;
    const int lane = tid & 31, wid = tid >> 5;
    const int wm = wid & 1;
    const int wn = wid >> 1;
    const long rowA = (long)blockIdx.y * 128;
    const long colB = (long)blockIdx.x * 128;
    const int K2  = 2 * K;
    const int nch = K >> 6;
    const int C   = 3 * nch;

    // per-thread load descriptors (hoisted out of the chunk loop)
    const int seg = tid & 7;
    const int r0  = tid >> 3;               // 0..31
    const __nv_bfloat16* aPtr[4];
    const __nv_bfloat16* bPtr[4];
    int aSz[4], bSz[4];
    uint32_t so[4];
#pragma unroll
    for (int u = 0; u < 4; u++) {
        int row = r0 + u * 32;
        long gr = rowA + row;
        long gm = colB + row;
        aPtr[u] = A + (gr < R ? gr : 0) * (long)K2 + seg * 8;
        bPtr[u] = B + (gm < M ? gm : 0) * (long)K2 + seg * 8;
        aSz[u] = (gr < R) ? 16 : 0;
        bSz[u] = (gm < M) ? 16 : 0;
        so[u] = (uint32_t)(row * SROW + seg * 8) * 2;
    }

    float acc[4][4][4];
#pragma unroll
    for (int i = 0; i < 4; i++)
#pragma unroll
        for (int j = 0; j < 4; j++)
#pragma unroll
            for (int k = 0; k < 4; k++) acc[i][j][k] = 0.0f;

    auto ld_chunk = [&](int c, int stg) {
        int tt = c / nch, j = c - tt * nch;
        int ao = ((tt == 1) ? K : 0) + j * 64;   // term1: A-lo * B-hi
        int bo = ((tt == 2) ? K : 0) + j * 64;   // term2: A-hi * B-lo
        uint32_t bA = sbase + (uint32_t)stg * STAGE_BYTES;
        uint32_t bB = bA + AB_HALF;
#pragma unroll
        for (int u = 0; u < 4; u++) {
            cpa16z(bA + so[u], aPtr[u] + ao, aSz[u]);
            cpa16z(bB + so[u], bPtr[u] + bo, bSz[u]);
        }
        asm volatile("cp.async.commit_group;" ::: "memory");
    };

    ld_chunk(0, 0);
    ld_chunk(1, 1);                         // C >= 6 always

    const uint32_t aOffC = ((uint32_t)(wm * 64 + (lane & 15)) * SROW + (lane >> 4) * 8) * 2;
    const uint32_t bOffC = ((uint32_t)(wn * 32 + ((lane >> 4) & 1) * 8 + (lane & 7)) * SROW +
                            ((lane >> 3) & 1) * 8) * 2;

    int stg = 0;
    for (int c = 0; c < C; c++) {
        if (c + 1 < C) asm volatile("cp.async.wait_group 1;" ::: "memory");
        else           asm volatile("cp.async.wait_group 0;" ::: "memory");
        __syncthreads();
        if (c + 2 < C) {
            int s2 = stg + 2; if (s2 >= 3) s2 -= 3;
            ld_chunk(c + 2, s2);
        }
        uint32_t aBase = sbase + (uint32_t)stg * STAGE_BYTES + aOffC;
        uint32_t bBase = sbase + (uint32_t)stg * STAGE_BYTES + AB_HALF + bOffC;

        // software-pipelined ldsm over 4 k-steps
        uint32_t a[2][4][4], bq[2][2][4];
#pragma unroll
        for (int mt = 0; mt < 4; mt++) ldsm4(a[0][mt], aBase + (uint32_t)(mt * 16 * SROW) * 2);
#pragma unroll
        for (int nt = 0; nt < 2; nt++) ldsm4(bq[0][nt], bBase + (uint32_t)(nt * 16 * SROW) * 2);
#pragma unroll
        for (int ks = 0; ks < 4; ks++) {
            int cur = ks & 1, nxt = cur ^ 1;
            if (ks < 3) {
#pragma unroll
                for (int mt = 0; mt < 4; mt++)
                    ldsm4(a[nxt][mt], aBase + (uint32_t)(mt * 16 * SROW + (ks + 1) * 16) * 2);
#pragma unroll
                for (int nt = 0; nt < 2; nt++)
                    ldsm4(bq[nxt][nt], bBase + (uint32_t)(nt * 16 * SROW + (ks + 1) * 16) * 2);
            }
#pragma unroll
            for (int mt = 0; mt < 4; mt++)
#pragma unroll
                for (int j = 0; j < 4; j++)
                    mma16816(acc[mt][j], a[cur][mt], &bq[cur][j >> 1][(j & 1) * 2]);
        }
        if (++stg == 3) stg = 0;
    }

    // epilogue
#pragma unroll
    for (int mt = 0; mt < 4; mt++) {
        long r0e = rowA + wm * 64 + mt * 16 + (lane >> 2);
#pragma unroll
        for (int j = 0; j < 4; j++) {
            int col0 = (int)colB + wn * 32 + j * 8 + (lane & 3) * 2;
#pragma unroll
            for (int half = 0; half < 2; half++) {
                long r = r0e + half * 8;
                if (r >= R) continue;
#pragma unroll
                for (int cc = 0; cc < 2; cc++) {
                    int col = col0 + cc;
                    if (col >= M) continue;
                    float v = acc[mt][j][half * 2 + cc];
                    if (bias) v += __ldg(bias + col);
                    if (ACT) v = 0.5f * v * (1.0f + erff(v * 0.7071067811865475f));
                    if (MODE == 0) {
                        outF[r * (long)M + col] = v;
                    } else {
                        split_write(v, &outS[r * (long)(2 * M) + col],
                                       &outS[r * (long)(2 * M) + M + col]);
                    }
                }
            }
        }
    }
}

// ---------------- batched GCN aggregate + bias + LN + ReLU -> split bf16 ----------------
__global__ void __launch_bounds__(256)
k_gcn_agg_ln_relu(const float* __restrict__ hWAll,
                  const float* __restrict__ bias, const float* __restrict__ g,
                  const float* __restrict__ b, __nv_bfloat16* __restrict__ outAll) {
    const int t = blockIdx.x;
    const int d = threadIdx.x;
    const float* hW = hWAll + (size_t)blockIdx.y * Nn * Dd;
    __nv_bfloat16* out = outAll + (size_t)blockIdx.y * Nn * 512;

    float di = g_dinv[t];
    float acc = di * di * hW[(size_t)t * Dd + d];
    int e0 = g_rowp[t], e1 = g_rowp[t + 1];
#pragma unroll 4
    for (int e = e0; e < e1; e++) {
        int s = __ldg(&g_csrc[e]);
        float nm = __ldg(&g_cnorm[e]);
        acc += nm * __ldg(&hW[(size_t)s * Dd + d]);
    }
    acc += bias[d];

    __shared__ float red[16];
    __shared__ float mv[2];
    float sum = acc, sq = acc * acc;
#pragma unroll
    for (int o = 16; o; o >>= 1) {
        sum += __shfl_down_sync(0xffffffffu, sum, o);
        sq  += __shfl_down_sync(0xffffffffu, sq, o);
    }
    int lane = d & 31, wid = d >> 5;
    if (lane == 0) { red[wid] = sum; red[8 + wid] = sq; }
    __syncthreads();
    if (d == 0) {
        float s = 0.f, q = 0.f;
#pragma unroll
        for (int i = 0; i < 8; i++) { s += red[i]; q += red[8 + i]; }
        float m = s * (1.0f / 256.0f);
        float var = q * (1.0f / 256.0f) - m * m;
        mv[0] = m;
        mv[1] = rsqrtf(var + 1e-5f);
    }
    __syncthreads();
    float val = fmaxf((acc - mv[0]) * mv[1] * g[d] + b[d], 0.0f);
    split_write(val, &out[(size_t)t * 512 + d], &out[(size_t)t * 512 + 256 + d]);
}

// ---------------- GRU cell ----------------
__global__ void k_gru_cell(const float* __restrict__ gi, const float* __restrict__ gh,
                           const float* __restrict__ bhh, const float* __restrict__ hprev,
                           float* __restrict__ hnew, __nv_bfloat16* __restrict__ hs,
                           int first) {
    int idx = blockIdx.x * blockDim.x + threadIdx.x;
    if (idx >= Nn * Dd) return;
    int n = idx >> 8, d = idx & 255;
    const float* gir = gi + (size_t)n * 768;
    float ir = gir[d], iz = gir[256 + d], ig = gir[512 + d];
    float hr, hz, hg, hp;
    if (first) {
        hr = bhh[d]; hz = bhh[256 + d]; hg = bhh[512 + d]; hp = 0.f;
    } else {
        const float* ghr = gh + (size_t)n * 768;
        hr = ghr[d]; hz = ghr[256 + d]; hg = ghr[512 + d];
        hp = hprev[idx];
    }
    float r = 1.0f / (1.0f + expf(-(ir + hr)));
    float z = 1.0f / (1.0f + expf(-(iz + hz)));
    float ng = tanhf(ig + r * hg);
    float v = (1.0f - z) * ng + z * hp;
    hnew[idx] = v;
    split_write(v, &hs[(size_t)n * 512 + d], &hs[(size_t)n * 512 + 256 + d]);
}

// ---------------- tiny head GEMM: out[N,5] = in[N,64] @ W[5,64]^T + b ----------------
__global__ void __launch_bounds__(256)
k_head5(const float* __restrict__ in, const float* __restrict__ W,
        const float* __restrict__ bias, float* __restrict__ out) {
    __shared__ float sW[5 * 64];
    for (int i = threadIdx.x; i < 5 * 64; i += blockDim.x) sW[i] = W[i];
    __syncthreads();
    int gw = (blockIdx.x * blockDim.x + threadIdx.x) >> 5;
    int lane = threadIdx.x & 31;
    if (gw >= Nn) return;
    float x0 = in[(size_t)gw * 64 + lane];
    float x1 = in[(size_t)gw * 64 + 32 + lane];
#pragma unroll
    for (int m = 0; m < 5; m++) {
        float p = x0 * sW[m * 64 + lane] + x1 * sW[m * 64 + 32 + lane];
#pragma unroll
        for (int o = 16; o; o >>= 1) p += __shfl_down_sync(0xffffffffu, p, o);
        if (lane == 0) out[(size_t)gw * 5 + m] = p + bias[m];
    }
}

// ---------------- host orchestration ----------------
template <typename T>
static T* symp(const void* sym) {
    void* p = nullptr;
    cudaGetSymbolAddress(&p, sym);
    return (T*)p;
}

extern "C" void kernel_launch(void* const* d_in, const int* in_sizes, int n_in,
                              void* d_out, int out_size) {
    const float* x    = (const float*)d_in[0];
    const int*   esrc = (const int*)d_in[1];
    const int*   edst = (const int*)d_in[2];
    const float* ew   = (const float*)d_in[3];
    const float* gcnW = (const float*)d_in[4];
    const float* gcnb = (const float*)d_in[5];
    const float* lng  = (const float*)d_in[6];
    const float* lnb  = (const float*)d_in[7];
    const float* Wih  = (const float*)d_in[8];
    const float* Whh  = (const float*)d_in[9];
    const float* bih  = (const float*)d_in[10];
    const float* bhh  = (const float*)d_in[11];
    const float* fc1W = (const float*)d_in[12];
    const float* fc1b = (const float*)d_in[13];
    const float* fc2W = (const float*)d_in[14];
    const float* fc2b = (const float*)d_in[15];
    const float* fc3W = (const float*)d_in[16];
    const float* fc3b = (const float*)d_in[17];
    const float* dh1W = (const float*)d_in[18];
    const float* dh1b = (const float*)d_in[19];
    const float* dh2W = (const float*)d_in[20];
    const float* dh2b = (const float*)d_in[21];

    float* outF = (float*)d_out;
    float* outD = outF + (size_t)Nn * Hh;

    float* tmpW  = symp<float>(g_tmpW);
    float* giAll = symp<float>(g_giAll);
    float* gh    = symp<float>(g_gh);
    float* h1    = symp<float>(g_h1);
    float* h2    = symp<float>(g_h2);
    float* f2    = symp<float>(g_f2);
    float* d1    = symp<float>(g_d1);
    __nv_bfloat16* xs    = symp<__nv_bfloat16>(g_xs);
    __nv_bfloat16* aggA  = symp<__nv_bfloat16>(g_aggA);
    __nv_bfloat16* seqs  = symp<__nv_bfloat16>(g_seqs);
    __nv_bfloat16* hs    = symp<__nv_bfloat16>(g_hs);
    __nv_bfloat16* f1s   = symp<__nv_bfloat16>(g_f1s);
    __nv_bfloat16* gcnWs = symp<__nv_bfloat16>(g_gcnWs);
    __nv_bfloat16* Wihs  = symp<__nv_bfloat16>(g_Wihs);
    __nv_bfloat16* Whhs  = symp<__nv_bfloat16>(g_Whhs);
    __nv_bfloat16* fc1Ws = symp<__nv_bfloat16>(g_fc1Ws);
    __nv_bfloat16* fc2Ws = symp<__nv_bfloat16>(g_fc2Ws);
    __nv_bfloat16* dh1Ws = symp<__nv_bfloat16>(g_dh1Ws);

    cudaFuncSetAttribute(gemm_mma, cudaFuncAttributeMaxDynamicSharedMemorySize, GEMM_SMEM);

    const int TB = 256;
    const int gN = (Nn + TB - 1) / TB;
    const int gE = (Ee + TB - 1) / TB;

    // graph preprocessing -> CSR
    k_init_deg_cnt<<<gN, TB>>>();
    k_edge_deg_cnt<<<gE, TB>>>(edst, ew);
    k_dinv<<<gN, TB>>>();
    k_scan<<<1, 1024>>>();
    k_copy_fill<<<gN, TB>>>();
    k_fill_csr<<<gE, TB>>>(esrc, edst, ew);

    // weight splits (tiny)
    for (int l = 0; l < 3; l++)
        k_splitT<<<(256 * 256 + TB - 1) / TB, TB>>>(gcnW + (size_t)l * 256 * 256,
                                                    gcnWs + (size_t)l * 256 * 512, 256, 256);
    k_split<<<(768 * 256 + TB - 1) / TB, TB>>>(Wih,  Wihs,  (long)768 * 256, 256);
    k_split<<<(768 * 256 + TB - 1) / TB, TB>>>(Whh,  Whhs,  (long)768 * 256, 256);
    k_split<<<(128 * 256 + TB - 1) / TB, TB>>>(fc1W, fc1Ws, (long)128 * 256, 256);
    k_split<<<(64 * 128 + TB - 1) / TB, TB>>>(fc2W, fc2Ws, (long)64 * 128, 128);
    k_split<<<(64 * 256 + TB - 1) / TB, TB>>>(dh1W, dh1Ws, (long)64 * 256, 256);

    dim3 blk(256);
    const int RB4 = (SN + 127) / 128;   // 625
    const int RB1 = (Nn + 127) / 128;   // 157
    dim3 gGCN(2, RB4);
    dim3 gGI(6, RB4);
    dim3 gGRU(6, RB1);
    dim3 gH1(1, RB1);
    dim3 gAgg(Nn, Ss);

    // batched GCN stack
    k_split<<<((long)SN * Dd + TB - 1) / TB, TB>>>(x, xs, (long)SN * Dd, 256);
    gemm_mma<<<gGCN, blk, GEMM_SMEM>>>(xs, gcnWs + 0 * 256 * 512, nullptr, tmpW, nullptr,
                                       SN, 256, 256, 0, 0);
    k_gcn_agg_ln_relu<<<gAgg, 256>>>(tmpW, gcnb + 0 * Dd, lng + 0 * Dd, lnb + 0 * Dd, aggA);
    gemm_mma<<<gGCN, blk, GEMM_SMEM>>>(aggA, gcnWs + 1 * 256 * 512, nullptr, tmpW, nullptr,
                                       SN, 256, 256, 0, 0);
    k_gcn_agg_ln_relu<<<gAgg, 256>>>(tmpW, gcnb + 1 * Dd, lng + 1 * Dd, lnb + 1 * Dd, aggA);
    gemm_mma<<<gGCN, blk, GEMM_SMEM>>>(aggA, gcnWs + 2 * 256 * 512, nullptr, tmpW, nullptr,
                                       SN, 256, 256, 0, 0);
    k_gcn_agg_ln_relu<<<gAgg, 256>>>(tmpW, gcnb + 2 * Dd, lng + 2 * Dd, lnb + 2 * Dd, seqs);

    // gi for ALL timesteps in one GEMM
    gemm_mma<<<gGI, blk, GEMM_SMEM>>>(seqs, Wihs, bih, giAll, nullptr, SN, 768, 256, 0, 0);

    // GRU recurrence
    const int gCell = (Nn * Dd + TB - 1) / TB;
    k_gru_cell<<<gCell, TB>>>(giAll, gh, bhh, h1, h1, hs, 1);
    for (int t = 1; t < Ss; t++) {
        float* hp = (t & 1) ? h1 : h2;
        float* hn = (t & 1) ? h2 : h1;
        gemm_mma<<<gGRU, blk, GEMM_SMEM>>>(hs, Whhs, bhh, gh, nullptr, Nn, 768, 256, 0, 0);
        k_gru_cell<<<gCell, TB>>>(giAll + (size_t)t * Nn * 768, gh, bhh, hp, hn, hs, 0);
    }

    // Forecast head
    gemm_mma<<<gH1, blk, GEMM_SMEM>>>(hs, fc1Ws, fc1b, nullptr, f1s, Nn, 128, 256, 1, 1);
    gemm_mma<<<gH1, blk, GEMM_SMEM>>>(f1s, fc2Ws, fc2b, f2, nullptr, Nn, 64, 128, 1, 0);
    k_head5<<<(Nn * 32 + TB - 1) / TB, TB>>>(f2, fc3W, fc3b, outF);

    // Direction head
    gemm_mma<<<gH1, blk, GEMM_SMEM>>>(hs, dh1Ws, dh1b, d1, nullptr, Nn, 64, 256, 1, 0);
    k_head5<<<(Nn * 32 + TB - 1) / TB, TB>>>(d1, dh2W, dh2b, outD);
}

// round 6
// speedup vs baseline: 1.0139x; 1.0139x over previous
#include <cuda_runtime.h>
#include <cuda_bf16.h>
#include <math.h>
#include <stdint.h>

#define Nn 20000
#define Dd 256
#define Ss 4
#define Ee 320000
#define Hh 5
#define SN (Ss * Nn)

// ---------------- scratch (device globals; no allocs allowed) ----------------
__device__ float g_deg[Nn];
__device__ float g_dinv[Nn];
__device__ int   g_cnt[Nn];
__device__ int   g_rowp[Nn + 1];
__device__ int   g_fill[Nn];
__device__ int   g_csrc[Ee];
__device__ float g_cnorm[Ee];

__device__ float g_tmpW[SN * Dd];
__device__ float g_giAll[SN * 3 * Dd];
__device__ float g_gh[Nn * 3 * Dd];
__device__ float g_h1[Nn * Dd];
__device__ float g_h2[Nn * Dd];
__device__ float g_f2[Nn * 64];
__device__ float g_d1[Nn * 64];
__device__ float g_cb[192];                     // fused fc1|dh1 bias

// split-bf16 activations: layout [rows, 2K] = [hi | lo]
__device__ __nv_bfloat16 g_xs[SN * 512];
__device__ __nv_bfloat16 g_aggA[SN * 512];
__device__ __nv_bfloat16 g_seqs[SN * 512];
__device__ __nv_bfloat16 g_hs[Nn * 512];
__device__ __nv_bfloat16 g_f1s[Nn * 256];

// split-bf16 weights: [M, 2K]
__device__ __nv_bfloat16 g_gcnWs[3 * 256 * 512];
__device__ __nv_bfloat16 g_Wihs[768 * 512];
__device__ __nv_bfloat16 g_Whhs[768 * 512];
__device__ __nv_bfloat16 g_cWs[192 * 512];      // fused fc1(128)|dh1(64) weights
__device__ __nv_bfloat16 g_fc2Ws[64 * 256];

// ---------------- helpers ----------------
__device__ __forceinline__ void split_write(float v, __nv_bfloat16* hi, __nv_bfloat16* lo) {
    __nv_bfloat16 h = __float2bfloat16(v);
    *hi = h;
    *lo = __float2bfloat16(v - __bfloat162float(h));
}
__device__ __forceinline__ void ldsm4(uint32_t* r, uint32_t addr) {
    asm volatile("ldmatrix.sync.aligned.m8n8.x4.shared.b16 {%0,%1,%2,%3}, [%4];"
                 : "=r"(r[0]), "=r"(r[1]), "=r"(r[2]), "=r"(r[3]) : "r"(addr));
}
__device__ __forceinline__ void mma16816(float* c, const uint32_t* a, const uint32_t* b) {
    asm volatile(
        "mma.sync.aligned.m16n8k16.row.col.f32.bf16.bf16.f32 "
        "{%0,%1,%2,%3}, {%4,%5,%6,%7}, {%8,%9}, {%0,%1,%2,%3};"
        : "+f"(c[0]), "+f"(c[1]), "+f"(c[2]), "+f"(c[3])
        : "r"(a[0]), "r"(a[1]), "r"(a[2]), "r"(a[3]), "r"(b[0]), "r"(b[1]));
}
__device__ __forceinline__ void cpa16z(uint32_t dst, const void* src, int sz) {
    asm volatile("cp.async.cg.shared.global [%0], [%1], 16, %2;"
                 :: "r"(dst), "l"(src), "r"(sz));
}

// ---------------- graph preprocessing ----------------
__global__ void k_init_deg_cnt() {
    int i = blockIdx.x * blockDim.x + threadIdx.x;
    if (i < Nn) { g_deg[i] = 1.0f; g_cnt[i] = 0; }
}
__global__ void k_edge_deg_cnt(const int* __restrict__ dst, const float* __restrict__ w) {
    int e = blockIdx.x * blockDim.x + threadIdx.x;
    if (e < Ee) {
        int t = dst[e];
        atomicAdd(&g_deg[t], w[e]);
        atomicAdd(&g_cnt[t], 1);
    }
}
__global__ void k_dinv() {
    int i = blockIdx.x * blockDim.x + threadIdx.x;
    if (i < Nn) g_dinv[i] = rsqrtf(g_deg[i]);
}
__global__ void k_scan() {
    __shared__ int wsum[32];
    __shared__ int carry_sh;
    if (threadIdx.x == 0) carry_sh = 0;
    __syncthreads();
    const int lane = threadIdx.x & 31, wid = threadIdx.x >> 5;
    const int nw = blockDim.x >> 5;
    for (int base = 0; base < Nn; base += blockDim.x) {
        int i = base + threadIdx.x;
        int v = (i < Nn) ? g_cnt[i] : 0;
        int x = v;
#pragma unroll
        for (int o = 1; o < 32; o <<= 1) {
            int y = __shfl_up_sync(0xffffffffu, x, o);
            if (lane >= o) x += y;
        }
        if (lane == 31) wsum[wid] = x;
        __syncthreads();
        if (wid == 0) {
            int s = (lane < nw) ? wsum[lane] : 0;
#pragma unroll
            for (int o = 1; o < 32; o <<= 1) {
                int y = __shfl_up_sync(0xffffffffu, s, o);
                if (lane >= o) s += y;
            }
            wsum[lane] = s;
        }
        __syncthreads();
        int warp_off = (wid == 0) ? 0 : wsum[wid - 1];
        int carry = carry_sh;
        if (i < Nn) g_rowp[i] = carry + warp_off + x - v;
        __syncthreads();
        if (threadIdx.x == blockDim.x - 1) carry_sh = carry + wsum[nw - 1];
        __syncthreads();
    }
    if (threadIdx.x == 0) g_rowp[Nn] = carry_sh;
}
__global__ void k_copy_fill() {
    int i = blockIdx.x * blockDim.x + threadIdx.x;
    if (i < Nn) g_fill[i] = g_rowp[i];
}
__global__ void k_fill_csr(const int* __restrict__ src, const int* __restrict__ dst,
                           const float* __restrict__ w) {
    int e = blockIdx.x * blockDim.x + threadIdx.x;
    if (e < Ee) {
        int s = src[e], t = dst[e];
        int pos = atomicAdd(&g_fill[t], 1);
        g_csrc[pos]  = s;
        g_cnorm[pos] = g_dinv[s] * w[e] * g_dinv[t];
    }
}

// ---------------- split conversion kernels ----------------
__global__ void k_split(const float* __restrict__ in, __nv_bfloat16* __restrict__ out,
                        long total, int K) {
    long idx = (long)blockIdx.x * blockDim.x + threadIdx.x;
    if (idx >= total) return;
    long r = idx / K;
    int  c = (int)(idx - r * K);
    float v = in[idx];
    split_write(v, &out[r * 2 * K + c], &out[r * 2 * K + K + c]);
}
__global__ void k_splitT(const float* __restrict__ in, __nv_bfloat16* __restrict__ out,
                         int Kd, int Md) {
    long idx = (long)blockIdx.x * blockDim.x + threadIdx.x;
    if (idx >= (long)Kd * Md) return;
    int k = (int)(idx / Md);
    int m = (int)(idx - (long)k * Md);
    float v = in[idx];
    split_write(v, &out[(long)m * 2 * Kd + k], &out[(long)m * 2 * Kd + Kd + k]);
}

// ---------------- bf16 mma.sync GEMM with 3-term split (R4 best-measured core) ----
// C[R,M] = A[R,K] @ B[M,K]^T; A/B split: [rows, 2K] = [hi | lo].
// Block 128x128, K-chunk 64; 256 thr, 8 warps (2M x 4N), warp 64x32. 2-stage.
// MODE 0: fp32 outF [R,M].  MODE 1: split bf16 outS [R,2M].  ACT 1 = exact GELU.
// MODE 3 (fused heads, M=192): col<128 -> split to outS [R,256]; col>=128 ->
//        fp32 to outF [R,64] at col-128.
#define SROW 72
#define ABUF (128 * SROW)
#define GEMM_SMEM (4 * ABUF * 2)
__global__ void __launch_bounds__(256)
gemm_mma(const __nv_bfloat16* __restrict__ A, const __nv_bfloat16* __restrict__ B,
         const float* __restrict__ bias, float* __restrict__ outF,
         __nv_bfloat16* __restrict__ outS, int R, int M, int K, int ACT, int MODE) {
    extern __shared__ __align__(16) __nv_bfloat16 smg[];
    const uint32_t sbase = (uint32_t)__cvta_generic_to_shared(smg);

    const int tid  = threadIdx.x;
    const int lane = tid & 31, wid = tid >> 5;
    const int wm = wid & 1;
    const int wn = wid >> 1;
    const long rowA = (long)blockIdx.y * 128;
    const long colB = (long)blockIdx.x * 128;
    const int K2  = 2 * K;
    const int nch = K >> 6;
    const int C   = 3 * nch;

    float acc[4][4][4];
#pragma unroll
    for (int i = 0; i < 4; i++)
#pragma unroll
        for (int j = 0; j < 4; j++)
#pragma unroll
            for (int k = 0; k < 4; k++) acc[i][j][k] = 0.0f;

    auto ld_chunk = [&](int c, int buf) {
        int tt = c / nch, j = c - tt * nch;
        int ao = ((tt == 1) ? K : 0) + j * 64;
        int bo = ((tt == 2) ? K : 0) + j * 64;
        uint32_t bA = sbase + (uint32_t)(buf * ABUF) * 2;
        uint32_t bB = sbase + (uint32_t)((2 + buf) * ABUF) * 2;
#pragma unroll
        for (int u = 0; u < 4; u++) {
            int task = (u << 8) + tid;
            int row = task >> 3, seg = task & 7;
            uint32_t so = (uint32_t)(row * SROW + seg * 8) * 2;
            long gr = rowA + row;
            cpa16z(bA + so, A + (gr < R ? gr : 0) * (long)K2 + ao + seg * 8, (gr < R) ? 16 : 0);
            long gm = colB + row;
            cpa16z(bB + so, B + (gm < M ? gm : 0) * (long)K2 + bo + seg * 8, (gm < M) ? 16 : 0);
        }
        asm volatile("cp.async.commit_group;" ::: "memory");
    };

    ld_chunk(0, 0);

    const uint32_t aOffC = ((uint32_t)(wm * 64 + (lane & 15)) * SROW + (lane >> 4) * 8) * 2;
    const uint32_t bOffC = ((uint32_t)(wn * 32 + ((lane >> 4) & 1) * 8 + (lane & 7)) * SROW +
                            ((lane >> 3) & 1) * 8) * 2;

    for (int c = 0; c < C; c++) {
        int buf = c & 1;
        if (c + 1 < C) {
            ld_chunk(c + 1, buf ^ 1);
            asm volatile("cp.async.wait_group 1;" ::: "memory");
        } else {
            asm volatile("cp.async.wait_group 0;" ::: "memory");
        }
        __syncthreads();
        uint32_t aBase = sbase + (uint32_t)(buf * ABUF) * 2 + aOffC;
        uint32_t bBase = sbase + (uint32_t)((2 + buf) * ABUF) * 2 + bOffC;
#pragma unroll
        for (int ks = 0; ks < 4; ks++) {
            uint32_t a[4][4], bf[2][4];
#pragma unroll
            for (int mt = 0; mt < 4; mt++)
                ldsm4(a[mt], aBase + (uint32_t)(mt * 16 * SROW + ks * 16) * 2);
#pragma unroll
            for (int nt = 0; nt < 2; nt++)
                ldsm4(bf[nt], bBase + (uint32_t)(nt * 16 * SROW + ks * 16) * 2);
#pragma unroll
            for (int mt = 0; mt < 4; mt++)
#pragma unroll
                for (int j = 0; j < 4; j++)
                    mma16816(acc[mt][j], a[mt], &bf[j >> 1][(j & 1) * 2]);
        }
        __syncthreads();
    }

    // epilogue
#pragma unroll
    for (int mt = 0; mt < 4; mt++) {
        long r0e = rowA + wm * 64 + mt * 16 + (lane >> 2);
#pragma unroll
        for (int j = 0; j < 4; j++) {
            int col0 = (int)colB + wn * 32 + j * 8 + (lane & 3) * 2;
#pragma unroll
            for (int half = 0; half < 2; half++) {
                long r = r0e + half * 8;
                if (r >= R) continue;
#pragma unroll
                for (int cc = 0; cc < 2; cc++) {
                    int col = col0 + cc;
                    if (col >= M) continue;
                    float v = acc[mt][j][half * 2 + cc];
                    if (bias) v += __ldg(bias + col);
                    if (ACT) v = 0.5f * v * (1.0f + erff(v * 0.7071067811865475f));
                    if (MODE == 0) {
                        outF[r * (long)M + col] = v;
                    } else if (MODE == 1) {
                        split_write(v, &outS[r * (long)(2 * M) + col],
                                       &outS[r * (long)(2 * M) + M + col]);
                    } else {   // MODE 3: fused fc1|dh1
                        if (col < 128)
                            split_write(v, &outS[r * 256 + col], &outS[r * 256 + 128 + col]);
                        else
                            outF[r * 64 + (col - 128)] = v;
                    }
                }
            }
        }
    }
}

// ---------------- batched GCN aggregate + bias + LN + ReLU -> split bf16 ----------------
__global__ void __launch_bounds__(256)
k_gcn_agg_ln_relu(const float* __restrict__ hWAll,
                  const float* __restrict__ bias, const float* __restrict__ g,
                  const float* __restrict__ b, __nv_bfloat16* __restrict__ outAll) {
    const int t = blockIdx.x;
    const int d = threadIdx.x;
    const float* hW = hWAll + (size_t)blockIdx.y * Nn * Dd;
    __nv_bfloat16* out = outAll + (size_t)blockIdx.y * Nn * 512;

    float di = g_dinv[t];
    float acc = di * di * hW[(size_t)t * Dd + d];
    int e0 = g_rowp[t], e1 = g_rowp[t + 1];
#pragma unroll 4
    for (int e = e0; e < e1; e++) {
        int s = __ldg(&g_csrc[e]);
        float nm = __ldg(&g_cnorm[e]);
        acc += nm * __ldg(&hW[(size_t)s * Dd + d]);
    }
    acc += bias[d];

    __shared__ float red[16];
    __shared__ float mv[2];
    float sum = acc, sq = acc * acc;
#pragma unroll
    for (int o = 16; o; o >>= 1) {
        sum += __shfl_down_sync(0xffffffffu, sum, o);
        sq  += __shfl_down_sync(0xffffffffu, sq, o);
    }
    int lane = d & 31, wid = d >> 5;
    if (lane == 0) { red[wid] = sum; red[8 + wid] = sq; }
    __syncthreads();
    if (d == 0) {
        float s = 0.f, q = 0.f;
#pragma unroll
        for (int i = 0; i < 8; i++) { s += red[i]; q += red[8 + i]; }
        float m = s * (1.0f / 256.0f);
        float var = q * (1.0f / 256.0f) - m * m;
        mv[0] = m;
        mv[1] = rsqrtf(var + 1e-5f);
    }
    __syncthreads();
    float val = fmaxf((acc - mv[0]) * mv[1] * g[d] + b[d], 0.0f);
    split_write(val, &out[(size_t)t * 512 + d], &out[(size_t)t * 512 + 256 + d]);
}

// ---------------- GRU cell ----------------
__global__ void k_gru_cell(const float* __restrict__ gi, const float* __restrict__ gh,
                           const float* __restrict__ bhh, const float* __restrict__ hprev,
                           float* __restrict__ hnew, __nv_bfloat16* __restrict__ hs,
                           int first) {
    int idx = blockIdx.x * blockDim.x + threadIdx.x;
    if (idx >= Nn * Dd) return;
    int n = idx >> 8, d = idx & 255;
    const float* gir = gi + (size_t)n * 768;
    float ir = gir[d], iz = gir[256 + d], ig = gir[512 + d];
    float hr, hz, hg, hp;
    if (first) {
        hr = bhh[d]; hz = bhh[256 + d]; hg = bhh[512 + d]; hp = 0.f;
    } else {
        const float* ghr = gh + (size_t)n * 768;
        hr = ghr[d]; hz = ghr[256 + d]; hg = ghr[512 + d];
        hp = hprev[idx];
    }
    float r = 1.0f / (1.0f + expf(-(ir + hr)));
    float z = 1.0f / (1.0f + expf(-(iz + hz)));
    float ng = tanhf(ig + r * hg);
    float v = (1.0f - z) * ng + z * hp;
    hnew[idx] = v;
    split_write(v, &hs[(size_t)n * 512 + d], &hs[(size_t)n * 512 + 256 + d]);
}

// ---------------- tiny head GEMM: out[N,5] = in[N,64] @ W[5,64]^T + b ----------------
__global__ void __launch_bounds__(256)
k_head5(const float* __restrict__ in, const float* __restrict__ W,
        const float* __restrict__ bias, float* __restrict__ out) {
    __shared__ float sW[5 * 64];
    for (int i = threadIdx.x; i < 5 * 64; i += blockDim.x) sW[i] = W[i];
    __syncthreads();
    int gw = (blockIdx.x * blockDim.x + threadIdx.x) >> 5;
    int lane = threadIdx.x & 31;
    if (gw >= Nn) return;
    float x0 = in[(size_t)gw * 64 + lane];
    float x1 = in[(size_t)gw * 64 + 32 + lane];
#pragma unroll
    for (int m = 0; m < 5; m++) {
        float p = x0 * sW[m * 64 + lane] + x1 * sW[m * 64 + 32 + lane];
#pragma unroll
        for (int o = 16; o; o >>= 1) p += __shfl_down_sync(0xffffffffu, p, o);
        if (lane == 0) out[(size_t)gw * 5 + m] = p + bias[m];
    }
}

// ---------------- host orchestration ----------------
template <typename T>
static T* symp(const void* sym) {
    void* p = nullptr;
    cudaGetSymbolAddress(&p, sym);
    return (T*)p;
}

extern "C" void kernel_launch(void* const* d_in, const int* in_sizes, int n_in,
                              void* d_out, int out_size) {
    const float* x    = (const float*)d_in[0];
    const int*   esrc = (const int*)d_in[1];
    const int*   edst = (const int*)d_in[2];
    const float* ew   = (const float*)d_in[3];
    const float* gcnW = (const float*)d_in[4];
    const float* gcnb = (const float*)d_in[5];
    const float* lng  = (const float*)d_in[6];
    const float* lnb  = (const float*)d_in[7];
    const float* Wih  = (const float*)d_in[8];
    const float* Whh  = (const float*)d_in[9];
    const float* bih  = (const float*)d_in[10];
    const float* bhh  = (const float*)d_in[11];
    const float* fc1W = (const float*)d_in[12];
    const float* fc1b = (const float*)d_in[13];
    const float* fc2W = (const float*)d_in[14];
    const float* fc2b = (const float*)d_in[15];
    const float* fc3W = (const float*)d_in[16];
    const float* fc3b = (const float*)d_in[17];
    const float* dh1W = (const float*)d_in[18];
    const float* dh1b = (const float*)d_in[19];
    const float* dh2W = (const float*)d_in[20];
    const float* dh2b = (const float*)d_in[21];

    float* outF = (float*)d_out;
    float* outD = outF + (size_t)Nn * Hh;

    float* tmpW  = symp<float>(g_tmpW);
    float* giAll = symp<float>(g_giAll);
    float* gh    = symp<float>(g_gh);
    float* h1    = symp<float>(g_h1);
    float* h2    = symp<float>(g_h2);
    float* f2    = symp<float>(g_f2);
    float* d1    = symp<float>(g_d1);
    float* cb    = symp<float>(g_cb);
    __nv_bfloat16* xs    = symp<__nv_bfloat16>(g_xs);
    __nv_bfloat16* aggA  = symp<__nv_bfloat16>(g_aggA);
    __nv_bfloat16* seqs  = symp<__nv_bfloat16>(g_seqs);
    __nv_bfloat16* hs    = symp<__nv_bfloat16>(g_hs);
    __nv_bfloat16* f1s   = symp<__nv_bfloat16>(g_f1s);
    __nv_bfloat16* gcnWs = symp<__nv_bfloat16>(g_gcnWs);
    __nv_bfloat16* Wihs  = symp<__nv_bfloat16>(g_Wihs);
    __nv_bfloat16* Whhs  = symp<__nv_bfloat16>(g_Whhs);
    __nv_bfloat16* cWs   = symp<__nv_bfloat16>(g_cWs);
    __nv_bfloat16* fc2Ws = symp<__nv_bfloat16>(g_fc2Ws);

    cudaFuncSetAttribute(gemm_mma, cudaFuncAttributeMaxDynamicSharedMemorySize, GEMM_SMEM);

    const int TB = 256;
    const int gN = (Nn + TB - 1) / TB;
    const int gE = (Ee + TB - 1) / TB;

    dim3 blk(256);
    const int RB4 = (SN + 127) / 128;   // 625
    const int RB1 = (Nn + 127) / 128;   // 157
    dim3 gGCN(2, RB4);
    dim3 gGI(6, RB4);
    dim3 gGRU(6, RB1);
    dim3 gHC(2, RB1);    // fused heads, M=192 -> 2 col blocks
    dim3 gH1(1, RB1);
    dim3 gAgg(Nn, Ss);

    // ---- prologue ordered so the big GCN GEMM is the 4th kernel launch (ncu -s 5 target) ----
    k_splitT<<<(256 * 256 + TB - 1) / TB, TB>>>(gcnW, gcnWs, 256, 256);                 // #1
    k_split<<<((long)SN * Dd + TB - 1) / TB, TB>>>(x, xs, (long)SN * Dd, 256);          // #2
    k_splitT<<<(256 * 256 + TB - 1) / TB, TB>>>(gcnW + 256 * 256,
                                                gcnWs + 256 * 512, 256, 256);           // #3
    gemm_mma<<<gGCN, blk, GEMM_SMEM>>>(xs, gcnWs, nullptr, tmpW, nullptr,
                                       SN, 256, 256, 0, 0);                             // #4 <- profile me
    k_splitT<<<(256 * 256 + TB - 1) / TB, TB>>>(gcnW + 2 * 256 * 256,
                                                gcnWs + 2 * 256 * 512, 256, 256);       // #5
    k_split<<<(768 * 256 + TB - 1) / TB, TB>>>(Wih,  Wihs,  (long)768 * 256, 256);
    k_split<<<(768 * 256 + TB - 1) / TB, TB>>>(Whh,  Whhs,  (long)768 * 256, 256);
    k_split<<<(128 * 256 + TB - 1) / TB, TB>>>(fc1W, cWs, (long)128 * 256, 256);
    k_split<<<(64 * 256 + TB - 1) / TB, TB>>>(dh1W, cWs + (size_t)128 * 512, (long)64 * 256, 256);
    k_split<<<(64 * 128 + TB - 1) / TB, TB>>>(fc2W, fc2Ws, (long)64 * 128, 128);
    cudaMemcpyAsync(cb, fc1b, 128 * sizeof(float), cudaMemcpyDeviceToDevice);
    cudaMemcpyAsync(cb + 128, dh1b, 64 * sizeof(float), cudaMemcpyDeviceToDevice);

    // graph preprocessing -> CSR (needed before first aggregation)
    k_init_deg_cnt<<<gN, TB>>>();
    k_edge_deg_cnt<<<gE, TB>>>(edst, ew);
    k_dinv<<<gN, TB>>>();
    k_scan<<<1, 1024>>>();
    k_copy_fill<<<gN, TB>>>();
    k_fill_csr<<<gE, TB>>>(esrc, edst, ew);

    // batched GCN stack (layer-0 GEMM already issued above)
    k_gcn_agg_ln_relu<<<gAgg, 256>>>(tmpW, gcnb + 0 * Dd, lng + 0 * Dd, lnb + 0 * Dd, aggA);
    gemm_mma<<<gGCN, blk, GEMM_SMEM>>>(aggA, gcnWs + 1 * 256 * 512, nullptr, tmpW, nullptr,
                                       SN, 256, 256, 0, 0);
    k_gcn_agg_ln_relu<<<gAgg, 256>>>(tmpW, gcnb + 1 * Dd, lng + 1 * Dd, lnb + 1 * Dd, aggA);
    gemm_mma<<<gGCN, blk, GEMM_SMEM>>>(aggA, gcnWs + 2 * 256 * 512, nullptr, tmpW, nullptr,
                                       SN, 256, 256, 0, 0);
    k_gcn_agg_ln_relu<<<gAgg, 256>>>(tmpW, gcnb + 2 * Dd, lng + 2 * Dd, lnb + 2 * Dd, seqs);

    // gi for ALL timesteps in one GEMM
    gemm_mma<<<gGI, blk, GEMM_SMEM>>>(seqs, Wihs, bih, giAll, nullptr, SN, 768, 256, 0, 0);

    // GRU recurrence
    const int gCell = (Nn * Dd + TB - 1) / TB;
    k_gru_cell<<<gCell, TB>>>(giAll, gh, bhh, h1, h1, hs, 1);
    for (int t = 1; t < Ss; t++) {
        float* hp = (t & 1) ? h1 : h2;
        float* hn = (t & 1) ? h2 : h1;
        gemm_mma<<<gGRU, blk, GEMM_SMEM>>>(hs, Whhs, bhh, gh, nullptr, Nn, 768, 256, 0, 0);
        k_gru_cell<<<gCell, TB>>>(giAll + (size_t)t * Nn * 768, gh, bhh, hp, hn, hs, 0);
    }

    // fused fc1|dh1 GEMM (M=192): cols<128 -> f1s (split, GELU); cols>=128 -> d1 (fp32, GELU)
    gemm_mma<<<gHC, blk, GEMM_SMEM>>>(hs, cWs, cb, d1, f1s, Nn, 192, 256, 1, 3);
    gemm_mma<<<gH1, blk, GEMM_SMEM>>>(f1s, fc2Ws, fc2b, f2, nullptr, Nn, 64, 128, 1, 0);
    k_head5<<<(Nn * 32 + TB - 1) / TB, TB>>>(f2, fc3W, fc3b, outF);
    k_head5<<<(Nn * 32 + TB - 1) / TB, TB>>>(d1, dh2W, dh2b, outD);
}

// round 7
// speedup vs baseline: 1.0199x; 1.0058x over previous
#include <cuda_runtime.h>
#include <cuda_bf16.h>
#include <math.h>
#include <stdint.h>

#define Nn 20000
#define Dd 256
#define Ss 4
#define Ee 320000
#define Hh 5
#define SN (Ss * Nn)

// ---------------- scratch (device globals; no allocs allowed) ----------------
__device__ float g_deg[Nn];
__device__ float g_dinv[Nn];
__device__ int   g_cnt[Nn];
__device__ int   g_rowp[Nn + 1];
__device__ int   g_fill[Nn];
__device__ int   g_csrc[Ee];
__device__ float g_cnorm[Ee];

__device__ float g_tmpW[SN * Dd];
__device__ float g_giAll[SN * 3 * Dd];
__device__ float g_gh[Nn * 3 * Dd];
__device__ float g_h1[Nn * Dd];
__device__ float g_h2[Nn * Dd];
__device__ float g_f2[Nn * 64];
__device__ float g_d1[Nn * 64];
__device__ float g_cb[192];                     // fused fc1|dh1 bias

// split-bf16 activations: layout [rows, 2K] = [hi | lo]
__device__ __nv_bfloat16 g_xs[SN * 512];
__device__ __nv_bfloat16 g_aggA[SN * 512];
__device__ __nv_bfloat16 g_seqs[SN * 512];
__device__ __nv_bfloat16 g_hs[Nn * 512];
__device__ __nv_bfloat16 g_f1s[Nn * 256];

// split-bf16 weights: [M, 2K]
__device__ __nv_bfloat16 g_gcnWs[3 * 256 * 512];
__device__ __nv_bfloat16 g_Wihs[768 * 512];
__device__ __nv_bfloat16 g_Whhs[768 * 512];
__device__ __nv_bfloat16 g_cWs[192 * 512];      // fused fc1(128)|dh1(64) weights
__device__ __nv_bfloat16 g_fc2Ws[64 * 256];

// ---------------- helpers ----------------
__device__ __forceinline__ void split_write(float v, __nv_bfloat16* hi, __nv_bfloat16* lo) {
    __nv_bfloat16 h = __float2bfloat16(v);
    *hi = h;
    *lo = __float2bfloat16(v - __bfloat162float(h));
}
__device__ __forceinline__ void ldsm4(uint32_t* r, uint32_t addr) {
    asm volatile("ldmatrix.sync.aligned.m8n8.x4.shared.b16 {%0,%1,%2,%3}, [%4];"
                 : "=r"(r[0]), "=r"(r[1]), "=r"(r[2]), "=r"(r[3]) : "r"(addr));
}
__device__ __forceinline__ void mma16816(float* c, const uint32_t* a, const uint32_t* b) {
    asm volatile(
        "mma.sync.aligned.m16n8k16.row.col.f32.bf16.bf16.f32 "
        "{%0,%1,%2,%3}, {%4,%5,%6,%7}, {%8,%9}, {%0,%1,%2,%3};"
        : "+f"(c[0]), "+f"(c[1]), "+f"(c[2]), "+f"(c[3])
        : "r"(a[0]), "r"(a[1]), "r"(a[2]), "r"(a[3]), "r"(b[0]), "r"(b[1]));
}
__device__ __forceinline__ void cpa16z(uint32_t dst, const void* src, int sz) {
    asm volatile("cp.async.cg.shared.global [%0], [%1], 16, %2;"
                 :: "r"(dst), "l"(src), "r"(sz));
}

// ---------------- graph preprocessing ----------------
__global__ void k_init_deg_cnt() {
    int i = blockIdx.x * blockDim.x + threadIdx.x;
    if (i < Nn) { g_deg[i] = 1.0f; g_cnt[i] = 0; }
}
__global__ void k_edge_deg_cnt(const int* __restrict__ dst, const float* __restrict__ w) {
    int e = blockIdx.x * blockDim.x + threadIdx.x;
    if (e < Ee) {
        int t = dst[e];
        atomicAdd(&g_deg[t], w[e]);
        atomicAdd(&g_cnt[t], 1);
    }
}
__global__ void k_dinv() {
    int i = blockIdx.x * blockDim.x + threadIdx.x;
    if (i < Nn) g_dinv[i] = rsqrtf(g_deg[i]);
}
__global__ void k_scan() {
    __shared__ int wsum[32];
    __shared__ int carry_sh;
    if (threadIdx.x == 0) carry_sh = 0;
    __syncthreads();
    const int lane = threadIdx.x & 31, wid = threadIdx.x >> 5;
    const int nw = blockDim.x >> 5;
    for (int base = 0; base < Nn; base += blockDim.x) {
        int i = base + threadIdx.x;
        int v = (i < Nn) ? g_cnt[i] : 0;
        int x = v;
#pragma unroll
        for (int o = 1; o < 32; o <<= 1) {
            int y = __shfl_up_sync(0xffffffffu, x, o);
            if (lane >= o) x += y;
        }
        if (lane == 31) wsum[wid] = x;
        __syncthreads();
        if (wid == 0) {
            int s = (lane < nw) ? wsum[lane] : 0;
#pragma unroll
            for (int o = 1; o < 32; o <<= 1) {
                int y = __shfl_up_sync(0xffffffffu, s, o);
                if (lane >= o) s += y;
            }
            wsum[lane] = s;
        }
        __syncthreads();
        int warp_off = (wid == 0) ? 0 : wsum[wid - 1];
        int carry = carry_sh;
        if (i < Nn) g_rowp[i] = carry + warp_off + x - v;
        __syncthreads();
        if (threadIdx.x == blockDim.x - 1) carry_sh = carry + wsum[nw - 1];
        __syncthreads();
    }
    if (threadIdx.x == 0) g_rowp[Nn] = carry_sh;
}
__global__ void k_copy_fill() {
    int i = blockIdx.x * blockDim.x + threadIdx.x;
    if (i < Nn) g_fill[i] = g_rowp[i];
}
__global__ void k_fill_csr(const int* __restrict__ src, const int* __restrict__ dst,
                           const float* __restrict__ w) {
    int e = blockIdx.x * blockDim.x + threadIdx.x;
    if (e < Ee) {
        int s = src[e], t = dst[e];
        int pos = atomicAdd(&g_fill[t], 1);
        g_csrc[pos]  = s;
        g_cnorm[pos] = g_dinv[s] * w[e] * g_dinv[t];
    }
}

// ---------------- split conversion kernels ----------------
__global__ void k_split(const float* __restrict__ in, __nv_bfloat16* __restrict__ out,
                        long total, int K) {
    long idx = (long)blockIdx.x * blockDim.x + threadIdx.x;
    if (idx >= total) return;
    long r = idx / K;
    int  c = (int)(idx - r * K);
    float v = in[idx];
    split_write(v, &out[r * 2 * K + c], &out[r * 2 * K + K + c]);
}
__global__ void k_splitT(const float* __restrict__ in, __nv_bfloat16* __restrict__ out,
                         int Kd, int Md) {
    long idx = (long)blockIdx.x * blockDim.x + threadIdx.x;
    if (idx >= (long)Kd * Md) return;
    int k = (int)(idx / Md);
    int m = (int)(idx - (long)k * Md);
    float v = in[idx];
    split_write(v, &out[(long)m * 2 * Kd + k], &out[(long)m * 2 * Kd + Kd + k]);
}

// ---------------- bf16 mma.sync GEMM with 3-term split ----------------
// C[R,M] = A[R,K] @ B[M,K]^T; A/B split: [rows, 2K] = [hi | lo].
// Block 128x128, K-chunk 64; 256 thr, 8 warps (2M x 4N), warp 64x32. 2-stage.
// __launch_bounds__(256, 2): 2 CTAs/SM (regs 128 x 512 thr = full RF;
// smem 2 x 73728 = 147KB < 228KB) -> 16 warps/SM to feed the tensor pipe.
// MODE 0: fp32 outF [R,M].  MODE 1: split bf16 outS [R,2M].  ACT 1 = exact GELU.
// MODE 3 (fused heads, M=192): col<128 -> split outS [R,256]; col>=128 -> fp32 outF [R,64].
#define SROW 72
#define ABUF (128 * SROW)
#define GEMM_SMEM (4 * ABUF * 2)
__global__ void __launch_bounds__(256, 2)
gemm_mma(const __nv_bfloat16* __restrict__ A, const __nv_bfloat16* __restrict__ B,
         const float* __restrict__ bias, float* __restrict__ outF,
         __nv_bfloat16* __restrict__ outS, int R, int M, int K, int ACT, int MODE) {
    extern __shared__ __align__(16) __nv_bfloat16 smg[];
    const uint32_t sbase = (uint32_t)__cvta_generic_to_shared(smg);

    const int tid  = threadIdx.x;
    const int lane = tid & 31, wid = tid >> 5;
    const int wm = wid & 1;
    const int wn = wid >> 1;
    const long rowA = (long)blockIdx.y * 128;
    const long colB = (long)blockIdx.x * 128;
    const int K2  = 2 * K;
    const int nch = K >> 6;
    const int C   = 3 * nch;

    float acc[4][4][4];
#pragma unroll
    for (int i = 0; i < 4; i++)
#pragma unroll
        for (int j = 0; j < 4; j++)
#pragma unroll
            for (int k = 0; k < 4; k++) acc[i][j][k] = 0.0f;

    auto ld_chunk = [&](int c, int buf) {
        int tt = c / nch, j = c - tt * nch;
        int ao = ((tt == 1) ? K : 0) + j * 64;
        int bo = ((tt == 2) ? K : 0) + j * 64;
        uint32_t bA = sbase + (uint32_t)(buf * ABUF) * 2;
        uint32_t bB = sbase + (uint32_t)((2 + buf) * ABUF) * 2;
#pragma unroll
        for (int u = 0; u < 4; u++) {
            int task = (u << 8) + tid;
            int row = task >> 3, seg = task & 7;
            uint32_t so = (uint32_t)(row * SROW + seg * 8) * 2;
            long gr = rowA + row;
            cpa16z(bA + so, A + (gr < R ? gr : 0) * (long)K2 + ao + seg * 8, (gr < R) ? 16 : 0);
            long gm = colB + row;
            cpa16z(bB + so, B + (gm < M ? gm : 0) * (long)K2 + bo + seg * 8, (gm < M) ? 16 : 0);
        }
        asm volatile("cp.async.commit_group;" ::: "memory");
    };

    ld_chunk(0, 0);

    const uint32_t aOffC = ((uint32_t)(wm * 64 + (lane & 15)) * SROW + (lane >> 4) * 8) * 2;
    const uint32_t bOffC = ((uint32_t)(wn * 32 + ((lane >> 4) & 1) * 8 + (lane & 7)) * SROW +
                            ((lane >> 3) & 1) * 8) * 2;

    for (int c = 0; c < C; c++) {
        int buf = c & 1;
        if (c + 1 < C) {
            ld_chunk(c + 1, buf ^ 1);
            asm volatile("cp.async.wait_group 1;" ::: "memory");
        } else {
            asm volatile("cp.async.wait_group 0;" ::: "memory");
        }
        __syncthreads();
        uint32_t aBase = sbase + (uint32_t)(buf * ABUF) * 2 + aOffC;
        uint32_t bBase = sbase + (uint32_t)((2 + buf) * ABUF) * 2 + bOffC;
#pragma unroll
        for (int ks = 0; ks < 4; ks++) {
            uint32_t a[4][4], bf[2][4];
#pragma unroll
            for (int mt = 0; mt < 4; mt++)
                ldsm4(a[mt], aBase + (uint32_t)(mt * 16 * SROW + ks * 16) * 2);
#pragma unroll
            for (int nt = 0; nt < 2; nt++)
                ldsm4(bf[nt], bBase + (uint32_t)(nt * 16 * SROW + ks * 16) * 2);
#pragma unroll
            for (int mt = 0; mt < 4; mt++)
#pragma unroll
                for (int j = 0; j < 4; j++)
                    mma16816(acc[mt][j], a[mt], &bf[j >> 1][(j & 1) * 2]);
        }
        __syncthreads();
    }

    // epilogue
#pragma unroll
    for (int mt = 0; mt < 4; mt++) {
        long r0e = rowA + wm * 64 + mt * 16 + (lane >> 2);
#pragma unroll
        for (int j = 0; j < 4; j++) {
            int col0 = (int)colB + wn * 32 + j * 8 + (lane & 3) * 2;
#pragma unroll
            for (int half = 0; half < 2; half++) {
                long r = r0e + half * 8;
                if (r >= R) continue;
#pragma unroll
                for (int cc = 0; cc < 2; cc++) {
                    int col = col0 + cc;
                    if (col >= M) continue;
                    float v = acc[mt][j][half * 2 + cc];
                    if (bias) v += __ldg(bias + col);
                    if (ACT) v = 0.5f * v * (1.0f + erff(v * 0.7071067811865475f));
                    if (MODE == 0) {
                        outF[r * (long)M + col] = v;
                    } else if (MODE == 1) {
                        split_write(v, &outS[r * (long)(2 * M) + col],
                                       &outS[r * (long)(2 * M) + M + col]);
                    } else {   // MODE 3: fused fc1|dh1
                        if (col < 128)
                            split_write(v, &outS[r * 256 + col], &outS[r * 256 + 128 + col]);
                        else
                            outF[r * 64 + (col - 128)] = v;
                    }
                }
            }
        }
    }
}

// ---------------- batched GCN aggregate + bias + LN + ReLU -> split bf16 ----------------
__global__ void __launch_bounds__(256)
k_gcn_agg_ln_relu(const float* __restrict__ hWAll,
                  const float* __restrict__ bias, const float* __restrict__ g,
                  const float* __restrict__ b, __nv_bfloat16* __restrict__ outAll) {
    const int t = blockIdx.x;
    const int d = threadIdx.x;
    const float* hW = hWAll + (size_t)blockIdx.y * Nn * Dd;
    __nv_bfloat16* out = outAll + (size_t)blockIdx.y * Nn * 512;

    float di = g_dinv[t];
    float acc = di * di * hW[(size_t)t * Dd + d];
    int e0 = g_rowp[t], e1 = g_rowp[t + 1];
#pragma unroll 4
    for (int e = e0; e < e1; e++) {
        int s = __ldg(&g_csrc[e]);
        float nm = __ldg(&g_cnorm[e]);
        acc += nm * __ldg(&hW[(size_t)s * Dd + d]);
    }
    acc += bias[d];

    __shared__ float red[16];
    __shared__ float mv[2];
    float sum = acc, sq = acc * acc;
#pragma unroll
    for (int o = 16; o; o >>= 1) {
        sum += __shfl_down_sync(0xffffffffu, sum, o);
        sq  += __shfl_down_sync(0xffffffffu, sq, o);
    }
    int lane = d & 31, wid = d >> 5;
    if (lane == 0) { red[wid] = sum; red[8 + wid] = sq; }
    __syncthreads();
    if (d == 0) {
        float s = 0.f, q = 0.f;
#pragma unroll
        for (int i = 0; i < 8; i++) { s += red[i]; q += red[8 + i]; }
        float m = s * (1.0f / 256.0f);
        float var = q * (1.0f / 256.0f) - m * m;
        mv[0] = m;
        mv[1] = rsqrtf(var + 1e-5f);
    }
    __syncthreads();
    float val = fmaxf((acc - mv[0]) * mv[1] * g[d] + b[d], 0.0f);
    split_write(val, &out[(size_t)t * 512 + d], &out[(size_t)t * 512 + 256 + d]);
}

// ---------------- GRU cell ----------------
__global__ void k_gru_cell(const float* __restrict__ gi, const float* __restrict__ gh,
                           const float* __restrict__ bhh, const float* __restrict__ hprev,
                           float* __restrict__ hnew, __nv_bfloat16* __restrict__ hs,
                           int first) {
    int idx = blockIdx.x * blockDim.x + threadIdx.x;
    if (idx >= Nn * Dd) return;
    int n = idx >> 8, d = idx & 255;
    const float* gir = gi + (size_t)n * 768;
    float ir = gir[d], iz = gir[256 + d], ig = gir[512 + d];
    float hr, hz, hg, hp;
    if (first) {
        hr = bhh[d]; hz = bhh[256 + d]; hg = bhh[512 + d]; hp = 0.f;
    } else {
        const float* ghr = gh + (size_t)n * 768;
        hr = ghr[d]; hz = ghr[256 + d]; hg = ghr[512 + d];
        hp = hprev[idx];
    }
    float r = 1.0f / (1.0f + expf(-(ir + hr)));
    float z = 1.0f / (1.0f + expf(-(iz + hz)));
    float ng = tanhf(ig + r * hg);
    float v = (1.0f - z) * ng + z * hp;
    hnew[idx] = v;
    split_write(v, &hs[(size_t)n * 512 + d], &hs[(size_t)n * 512 + 256 + d]);
}

// ---------------- tiny head GEMM: out[N,5] = in[N,64] @ W[5,64]^T + b ----------------
__global__ void __launch_bounds__(256)
k_head5(const float* __restrict__ in, const float* __restrict__ W,
        const float* __restrict__ bias, float* __restrict__ out) {
    __shared__ float sW[5 * 64];
    for (int i = threadIdx.x; i < 5 * 64; i += blockDim.x) sW[i] = W[i];
    __syncthreads();
    int gw = (blockIdx.x * blockDim.x + threadIdx.x) >> 5;
    int lane = threadIdx.x & 31;
    if (gw >= Nn) return;
    float x0 = in[(size_t)gw * 64 + lane];
    float x1 = in[(size_t)gw * 64 + 32 + lane];
#pragma unroll
    for (int m = 0; m < 5; m++) {
        float p = x0 * sW[m * 64 + lane] + x1 * sW[m * 64 + 32 + lane];
#pragma unroll
        for (int o = 16; o; o >>= 1) p += __shfl_down_sync(0xffffffffu, p, o);
        if (lane == 0) out[(size_t)gw * 5 + m] = p + bias[m];
    }
}

// ---------------- host orchestration ----------------
template <typename T>
static T* symp(const void* sym) {
    void* p = nullptr;
    cudaGetSymbolAddress(&p, sym);
    return (T*)p;
}

extern "C" void kernel_launch(void* const* d_in, const int* in_sizes, int n_in,
                              void* d_out, int out_size) {
    const float* x    = (const float*)d_in[0];
    const int*   esrc = (const int*)d_in[1];
    const int*   edst = (const int*)d_in[2];
    const float* ew   = (const float*)d_in[3];
    const float* gcnW = (const float*)d_in[4];
    const float* gcnb = (const float*)d_in[5];
    const float* lng  = (const float*)d_in[6];
    const float* lnb  = (const float*)d_in[7];
    const float* Wih  = (const float*)d_in[8];
    const float* Whh  = (const float*)d_in[9];
    const float* bih  = (const float*)d_in[10];
    const float* bhh  = (const float*)d_in[11];
    const float* fc1W = (const float*)d_in[12];
    const float* fc1b = (const float*)d_in[13];
    const float* fc2W = (const float*)d_in[14];
    const float* fc2b = (const float*)d_in[15];
    const float* fc3W = (const float*)d_in[16];
    const float* fc3b = (const float*)d_in[17];
    const float* dh1W = (const float*)d_in[18];
    const float* dh1b = (const float*)d_in[19];
    const float* dh2W = (const float*)d_in[20];
    const float* dh2b = (const float*)d_in[21];

    float* outF = (float*)d_out;
    float* outD = outF + (size_t)Nn * Hh;

    float* tmpW  = symp<float>(g_tmpW);
    float* giAll = symp<float>(g_giAll);
    float* gh    = symp<float>(g_gh);
    float* h1    = symp<float>(g_h1);
    float* h2    = symp<float>(g_h2);
    float* f2    = symp<float>(g_f2);
    float* d1    = symp<float>(g_d1);
    float* cb    = symp<float>(g_cb);
    __nv_bfloat16* xs    = symp<__nv_bfloat16>(g_xs);
    __nv_bfloat16* aggA  = symp<__nv_bfloat16>(g_aggA);
    __nv_bfloat16* seqs  = symp<__nv_bfloat16>(g_seqs);
    __nv_bfloat16* hs    = symp<__nv_bfloat16>(g_hs);
    __nv_bfloat16* f1s   = symp<__nv_bfloat16>(g_f1s);
    __nv_bfloat16* gcnWs = symp<__nv_bfloat16>(g_gcnWs);
    __nv_bfloat16* Wihs  = symp<__nv_bfloat16>(g_Wihs);
    __nv_bfloat16* Whhs  = symp<__nv_bfloat16>(g_Whhs);
    __nv_bfloat16* cWs   = symp<__nv_bfloat16>(g_cWs);
    __nv_bfloat16* fc2Ws = symp<__nv_bfloat16>(g_fc2Ws);

    cudaFuncSetAttribute(gemm_mma, cudaFuncAttributeMaxDynamicSharedMemorySize, GEMM_SMEM);

    const int TB = 256;
    const int gN = (Nn + TB - 1) / TB;
    const int gE = (Ee + TB - 1) / TB;

    dim3 blk(256);
    const int RB4 = (SN + 127) / 128;   // 625
    const int RB1 = (Nn + 127) / 128;   // 157
    dim3 gGCN(2, RB4);
    dim3 gGI(6, RB4);
    dim3 gGRU(6, RB1);
    dim3 gHC(2, RB1);
    dim3 gH1(1, RB1);
    dim3 gAgg(Nn, Ss);

    // ---- prologue ordered so the big GCN GEMM stays at launch slot #4 (ncu -s 5) ----
    k_splitT<<<(256 * 256 + TB - 1) / TB, TB>>>(gcnW, gcnWs, 256, 256);                 // #1
    k_split<<<((long)SN * Dd + TB - 1) / TB, TB>>>(x, xs, (long)SN * Dd, 256);          // #2
    k_splitT<<<(256 * 256 + TB - 1) / TB, TB>>>(gcnW + 256 * 256,
                                                gcnWs + 256 * 512, 256, 256);           // #3
    gemm_mma<<<gGCN, blk, GEMM_SMEM>>>(xs, gcnWs, nullptr, tmpW, nullptr,
                                       SN, 256, 256, 0, 0);                             // #4 <- profile
    k_splitT<<<(256 * 256 + TB - 1) / TB, TB>>>(gcnW + 2 * 256 * 256,
                                                gcnWs + 2 * 256 * 512, 256, 256);
    k_split<<<(768 * 256 + TB - 1) / TB, TB>>>(Wih,  Wihs,  (long)768 * 256, 256);
    k_split<<<(768 * 256 + TB - 1) / TB, TB>>>(Whh,  Whhs,  (long)768 * 256, 256);
    k_split<<<(128 * 256 + TB - 1) / TB, TB>>>(fc1W, cWs, (long)128 * 256, 256);
    k_split<<<(64 * 256 + TB - 1) / TB, TB>>>(dh1W, cWs + (size_t)128 * 512, (long)64 * 256, 256);
    k_split<<<(64 * 128 + TB - 1) / TB, TB>>>(fc2W, fc2Ws, (long)64 * 128, 128);
    cudaMemcpyAsync(cb, fc1b, 128 * sizeof(float), cudaMemcpyDeviceToDevice);
    cudaMemcpyAsync(cb + 128, dh1b, 64 * sizeof(float), cudaMemcpyDeviceToDevice);

    // graph preprocessing -> CSR
    k_init_deg_cnt<<<gN, TB>>>();
    k_edge_deg_cnt<<<gE, TB>>>(edst, ew);
    k_dinv<<<gN, TB>>>();
    k_scan<<<1, 1024>>>();
    k_copy_fill<<<gN, TB>>>();
    k_fill_csr<<<gE, TB>>>(esrc, edst, ew);

    // batched GCN stack (layer-0 GEMM already issued above)
    k_gcn_agg_ln_relu<<<gAgg, 256>>>(tmpW, gcnb + 0 * Dd, lng + 0 * Dd, lnb + 0 * Dd, aggA);
    gemm_mma<<<gGCN, blk, GEMM_SMEM>>>(aggA, gcnWs + 1 * 256 * 512, nullptr, tmpW, nullptr,
                                       SN, 256, 256, 0, 0);
    k_gcn_agg_ln_relu<<<gAgg, 256>>>(tmpW, gcnb + 1 * Dd, lng + 1 * Dd, lnb + 1 * Dd, aggA);
    gemm_mma<<<gGCN, blk, GEMM_SMEM>>>(aggA, gcnWs + 2 * 256 * 512, nullptr, tmpW, nullptr,
                                       SN, 256, 256, 0, 0);
    k_gcn_agg_ln_relu<<<gAgg, 256>>>(tmpW, gcnb + 2 * Dd, lng + 2 * Dd, lnb + 2 * Dd, seqs);

    // gi for ALL timesteps in one GEMM
    gemm_mma<<<gGI, blk, GEMM_SMEM>>>(seqs, Wihs, bih, giAll, nullptr, SN, 768, 256, 0, 0);

    // GRU recurrence
    const int gCell = (Nn * Dd + TB - 1) / TB;
    k_gru_cell<<<gCell, TB>>>(giAll, gh, bhh, h1, h1, hs, 1);
    for (int t = 1; t < Ss; t++) {
        float* hp = (t & 1) ? h1 : h2;
        float* hn = (t & 1) ? h2 : h1;
        gemm_mma<<<gGRU, blk, GEMM_SMEM>>>(hs, Whhs, bhh, gh, nullptr, Nn, 768, 256, 0, 0);
        k_gru_cell<<<gCell, TB>>>(giAll + (size_t)t * Nn * 768, gh, bhh, hp, hn, hs, 0);
    }

    // fused fc1|dh1 GEMM (M=192)
    gemm_mma<<<gHC, blk, GEMM_SMEM>>>(hs, cWs, cb, d1, f1s, Nn, 192, 256, 1, 3);
    gemm_mma<<<gH1, blk, GEMM_SMEM>>>(f1s, fc2Ws, fc2b, f2, nullptr, Nn, 64, 128, 1, 0);
    k_head5<<<(Nn * 32 + TB - 1) / TB, TB>>>(f2, fc3W, fc3b, outF);
    k_head5<<<(Nn * 32 + TB - 1) / TB, TB>>>(d1, dh2W, dh2b, outD);
}